// round 2
// baseline (speedup 1.0000x reference)
#include <cuda_runtime.h>
#include <cstddef>

// ---------------------------------------------------------------------------
// NCEAverageMultiview on GB300 — HBM-bound; gathers overlapped with bank copies
// via stream fork/join inside graph capture.
//
// d_out layout (fp32): out_v1 [B*KP1] | out_v2 [B*KP1] | new_mem_v1 [N*D] | new_mem_v2 [N*D]
// ---------------------------------------------------------------------------

__device__ double g_sum[2];

__global__ void init_sums_kernel() { g_sum[0] = 0.0; g_sum[1] = 0.0; }

#define DOT4(p, a) ((p).x*(a).x + (p).y*(a).y + (p).z*(a).z + (p).w*(a).w)

// 2 blocks per batch element b; 16 warps/b; each warp does 4 rows per iter
// (8 x 512B gathers in flight) for high MLP.
__global__ void __launch_bounds__(256) dot_exp_kernel(
    const float* __restrict__ v1, const float* __restrict__ v2,
    const float* __restrict__ m1, const float* __restrict__ m2,
    const int* __restrict__ y, const int* __restrict__ idx,
    float* __restrict__ out1, float* __restrict__ out2,
    int KP1)
{
    __shared__ double sred1[8], sred2[8];
    const int lane = threadIdx.x & 31;
    const int warp = threadIdx.x >> 5;
    const int b    = blockIdx.x >> 1;
    const int wib  = ((blockIdx.x & 1) << 3) + warp;   // 0..15
    const float invT = 1.0f / 0.07f;

    const float4 a1 = reinterpret_cast<const float4*>(v1 + (size_t)b * 128)[lane];
    const float4 a2 = reinterpret_cast<const float4*>(v2 + (size_t)b * 128)[lane];
    const int yb = y[b];
    const int* __restrict__ idxb = idx + (size_t)b * KP1;
    float* __restrict__ o1 = out1 + (size_t)b * KP1;
    float* __restrict__ o2 = out2 + (size_t)b * KP1;

    double acc1 = 0.0, acc2 = 0.0;

    for (int base = wib * 4; base < KP1; base += 64) {
        const int kk = base + (lane & 3);
        int iv = 0;
        if (kk < KP1) iv = (kk == 0) ? yb : __ldg(idxb + kk);
        const int i0 = __shfl_sync(0xffffffffu, iv, 0);
        const int i1 = __shfl_sync(0xffffffffu, iv, 1);
        const int i2 = __shfl_sync(0xffffffffu, iv, 2);
        const int i3 = __shfl_sync(0xffffffffu, iv, 3);

        // 8 x 512B gathers issued back-to-back
        const float4 q0 = __ldg(reinterpret_cast<const float4*>(m1 + (size_t)i0 * 128) + lane);
        const float4 q1 = __ldg(reinterpret_cast<const float4*>(m1 + (size_t)i1 * 128) + lane);
        const float4 q2 = __ldg(reinterpret_cast<const float4*>(m1 + (size_t)i2 * 128) + lane);
        const float4 q3 = __ldg(reinterpret_cast<const float4*>(m1 + (size_t)i3 * 128) + lane);
        const float4 r0 = __ldg(reinterpret_cast<const float4*>(m2 + (size_t)i0 * 128) + lane);
        const float4 r1 = __ldg(reinterpret_cast<const float4*>(m2 + (size_t)i1 * 128) + lane);
        const float4 r2 = __ldg(reinterpret_cast<const float4*>(m2 + (size_t)i2 * 128) + lane);
        const float4 r3 = __ldg(reinterpret_cast<const float4*>(m2 + (size_t)i3 * 128) + lane);

        // out_v1 = exp(<memory_v2[i], v1>/T); out_v2 = exp(<memory_v1[i], v2>/T)
        float u0 = DOT4(r0, a1), u1 = DOT4(r1, a1), u2 = DOT4(r2, a1), u3 = DOT4(r3, a1);
        float w0 = DOT4(q0, a2), w1 = DOT4(q1, a2), w2 = DOT4(q2, a2), w3 = DOT4(q3, a2);

        #pragma unroll
        for (int o = 16; o; o >>= 1) {
            u0 += __shfl_xor_sync(0xffffffffu, u0, o);
            u1 += __shfl_xor_sync(0xffffffffu, u1, o);
            u2 += __shfl_xor_sync(0xffffffffu, u2, o);
            u3 += __shfl_xor_sync(0xffffffffu, u3, o);
            w0 += __shfl_xor_sync(0xffffffffu, w0, o);
            w1 += __shfl_xor_sync(0xffffffffu, w1, o);
            w2 += __shfl_xor_sync(0xffffffffu, w2, o);
            w3 += __shfl_xor_sync(0xffffffffu, w3, o);
        }

        if (lane == 0) {
            const float eu[4] = { __expf(u0*invT), __expf(u1*invT), __expf(u2*invT), __expf(u3*invT) };
            const float ew[4] = { __expf(w0*invT), __expf(w1*invT), __expf(w2*invT), __expf(w3*invT) };
            #pragma unroll
            for (int j = 0; j < 4; ++j) {
                if (base + j < KP1) {
                    o1[base + j] = eu[j];
                    o2[base + j] = ew[j];
                    acc1 += (double)eu[j];
                    acc2 += (double)ew[j];
                }
            }
        }
    }

    if (lane == 0) { sred1[warp] = acc1; sred2[warp] = acc2; }
    __syncthreads();
    if (threadIdx.x == 0) {
        double t1 = 0.0, t2 = 0.0;
        #pragma unroll
        for (int j = 0; j < 8; ++j) { t1 += sred1[j]; t2 += sred2[j]; }
        atomicAdd(&g_sum[0], t1);
        atomicAdd(&g_sum[1], t2);
    }
}

// Copy both memory banks (streaming loads/stores: keep L2 for the gathers).
__global__ void __launch_bounds__(256) copy_kernel(
    float4* __restrict__ d1, const float4* __restrict__ s1,
    float4* __restrict__ d2, const float4* __restrict__ s2,
    size_t n4)
{
    size_t i = (size_t)blockIdx.x * blockDim.x + threadIdx.x;
    const size_t stride = (size_t)gridDim.x * blockDim.x;
    for (size_t j = i; j < 2 * n4; j += stride) {
        if (j < n4) __stcs(d1 + j, __ldcs(s1 + j));
        else        __stcs(d2 + (j - n4), __ldcs(s2 + (j - n4)));
    }
}

// Fused epilogue: blocks [0, normBlocks) normalize; rest do the momentum
// scatter update (one warp per b, last-duplicate-wins).
__global__ void __launch_bounds__(256) epilogue_kernel(
    float* __restrict__ out1, float* __restrict__ out2, int total, double nOutput,
    const float* __restrict__ v1, const float* __restrict__ v2,
    const float* __restrict__ m1, const float* __restrict__ m2,
    const int* __restrict__ y,
    float* __restrict__ om1, float* __restrict__ om2,
    int B, int normBlocks)
{
    if ((int)blockIdx.x < normBlocks) {
        const double cnt = (double)total;
        const float f1 = (float)(cnt / (g_sum[0] * nOutput));
        const float f2 = (float)(cnt / (g_sum[1] * nOutput));
        const int i = blockIdx.x * 256 + threadIdx.x;
        if (i < total) { out1[i] *= f1; out2[i] *= f2; }
        return;
    }

    const int warp = threadIdx.x >> 5;
    const int lane = threadIdx.x & 31;
    const int b = ((int)blockIdx.x - normBlocks) * 8 + warp;
    if (b >= B) return;
    const int yb = y[b];
    for (int b2 = b + 1; b2 < B; ++b2)
        if (y[b2] == yb) return;            // later duplicate wins

    {
        const float4 mv = reinterpret_cast<const float4*>(m1 + (size_t)yb * 128)[lane];
        const float4 vv = reinterpret_cast<const float4*>(v1 + (size_t)b  * 128)[lane];
        float4 p = { 0.5f*(mv.x+vv.x), 0.5f*(mv.y+vv.y), 0.5f*(mv.z+vv.z), 0.5f*(mv.w+vv.w) };
        float ss = p.x*p.x + p.y*p.y + p.z*p.z + p.w*p.w;
        #pragma unroll
        for (int o = 16; o; o >>= 1) ss += __shfl_xor_sync(0xffffffffu, ss, o);
        const float inv = 1.0f / sqrtf(ss);
        p.x *= inv; p.y *= inv; p.z *= inv; p.w *= inv;
        reinterpret_cast<float4*>(om1 + (size_t)yb * 128)[lane] = p;
    }
    {
        const float4 mv = reinterpret_cast<const float4*>(m2 + (size_t)yb * 128)[lane];
        const float4 vv = reinterpret_cast<const float4*>(v2 + (size_t)b  * 128)[lane];
        float4 p = { 0.5f*(mv.x+vv.x), 0.5f*(mv.y+vv.y), 0.5f*(mv.z+vv.z), 0.5f*(mv.w+vv.w) };
        float ss = p.x*p.x + p.y*p.y + p.z*p.z + p.w*p.w;
        #pragma unroll
        for (int o = 16; o; o >>= 1) ss += __shfl_xor_sync(0xffffffffu, ss, o);
        const float inv = 1.0f / sqrtf(ss);
        p.x *= inv; p.y *= inv; p.z *= inv; p.w *= inv;
        reinterpret_cast<float4*>(om2 + (size_t)yb * 128)[lane] = p;
    }
}

extern "C" void kernel_launch(void* const* d_in, const int* in_sizes, int n_in,
                              void* d_out, int out_size)
{
    const float* v1  = (const float*)d_in[0];
    const float* v2  = (const float*)d_in[1];
    const float* m1  = (const float*)d_in[2];
    const float* m2  = (const float*)d_in[3];
    const int*   y   = (const int*)d_in[4];
    const int*   idx = (const int*)d_in[5];

    const int B = in_sizes[4];                 // 256
    const int D = in_sizes[0] / B;             // 128
    const size_t ND = (size_t)in_sizes[2];     // N*D
    const int KP1 = in_sizes[5] / B;           // 4097
    const int Nout = (int)(ND / (size_t)D);    // 1,000,000

    float* out  = (float*)d_out;
    float* out1 = out;
    float* out2 = out + (size_t)B * KP1;
    float* om1  = out + 2 * (size_t)B * KP1;
    float* om2  = om1 + ND;

    // One-time side-stream + events (created outside capture: the first call
    // is the un-captured correctness run).
    static cudaStream_t s1 = nullptr;
    static cudaEvent_t eFork = nullptr, eJoin = nullptr;
    if (s1 == nullptr) {
        cudaStreamCreateWithFlags(&s1, cudaStreamNonBlocking);
        cudaEventCreateWithFlags(&eFork, cudaEventDisableTiming);
        cudaEventCreateWithFlags(&eJoin, cudaEventDisableTiming);
    }

    // Fork: copies run concurrently with the gather/dot kernel.
    cudaEventRecord(eFork, 0);
    cudaStreamWaitEvent(s1, eFork, 0);
    copy_kernel<<<1184, 256, 0, s1>>>((float4*)om1, (const float4*)m1,
                                      (float4*)om2, (const float4*)m2, ND / 4);
    cudaEventRecord(eJoin, s1);

    init_sums_kernel<<<1, 1>>>();
    dot_exp_kernel<<<2 * B, 256>>>(v1, v2, m1, m2, y, idx, out1, out2, KP1);

    // Join, then fused normalize + scatter-update.
    cudaStreamWaitEvent(0, eJoin, 0);
    const int total = B * KP1;
    const int normBlocks = (total + 255) / 256;
    const int updBlocks = (B + 7) / 8;
    epilogue_kernel<<<normBlocks + updBlocks, 256>>>(
        out1, out2, total, (double)Nout,
        v1, v2, m1, m2, y, om1, om2, B, normBlocks);
}

// round 3
// speedup vs baseline: 1.3170x; 1.3170x over previous
#include <cuda_runtime.h>
#include <cstddef>

// ---------------------------------------------------------------------------
// NCEAverageMultiview on GB300 — serial HBM-bound pipeline.
// d_out (fp32): out_v1 [B*KP1] | out_v2 [B*KP1] | new_mem_v1 [N*D] | new_mem_v2 [N*D]
// ---------------------------------------------------------------------------

__device__ double g_sum[2];
__device__ float  g_scale[2];

__global__ void init_sums_kernel() { g_sum[0] = 0.0; g_sum[1] = 0.0; }

__global__ void finalize_scale_kernel(int total, double nOutput) {
    const double cnt = (double)total;
    g_scale[0] = (float)(cnt / (g_sum[0] * nOutput));
    g_scale[1] = (float)(cnt / (g_sum[1] * nOutput));
}

#define DOT4(p, a) ((p).x*(a).x + (p).y*(a).y + (p).z*(a).z + (p).w*(a).w)

// 2 blocks per batch element; each warp handles 4 (b,k) rows per iteration,
// so 8 x 512B gathers are in flight per warp.
__global__ void __launch_bounds__(256) dot_exp_kernel(
    const float* __restrict__ v1, const float* __restrict__ v2,
    const float* __restrict__ m1, const float* __restrict__ m2,
    const int* __restrict__ y, const int* __restrict__ idx,
    float* __restrict__ out1, float* __restrict__ out2,
    int KP1)
{
    __shared__ double sred1[8], sred2[8];
    const int lane = threadIdx.x & 31;
    const int warp = threadIdx.x >> 5;
    const int b    = blockIdx.x >> 1;
    const int wib  = ((blockIdx.x & 1) << 3) + warp;   // 0..15
    const float invT = 1.0f / 0.07f;

    const float4 a1 = reinterpret_cast<const float4*>(v1 + (size_t)b * 128)[lane];
    const float4 a2 = reinterpret_cast<const float4*>(v2 + (size_t)b * 128)[lane];
    const int yb = y[b];
    const int* __restrict__ idxb = idx + (size_t)b * KP1;
    float* __restrict__ o1 = out1 + (size_t)b * KP1;
    float* __restrict__ o2 = out2 + (size_t)b * KP1;

    double acc1 = 0.0, acc2 = 0.0;

    for (int base = wib * 4; base < KP1; base += 64) {
        const int kk = base + (lane & 3);
        int iv = 0;
        if (kk < KP1) iv = (kk == 0) ? yb : __ldg(idxb + kk);
        const int i0 = __shfl_sync(0xffffffffu, iv, 0);
        const int i1 = __shfl_sync(0xffffffffu, iv, 1);
        const int i2 = __shfl_sync(0xffffffffu, iv, 2);
        const int i3 = __shfl_sync(0xffffffffu, iv, 3);

        const float4 q0 = __ldg(reinterpret_cast<const float4*>(m1 + (size_t)i0 * 128) + lane);
        const float4 q1 = __ldg(reinterpret_cast<const float4*>(m1 + (size_t)i1 * 128) + lane);
        const float4 q2 = __ldg(reinterpret_cast<const float4*>(m1 + (size_t)i2 * 128) + lane);
        const float4 q3 = __ldg(reinterpret_cast<const float4*>(m1 + (size_t)i3 * 128) + lane);
        const float4 r0 = __ldg(reinterpret_cast<const float4*>(m2 + (size_t)i0 * 128) + lane);
        const float4 r1 = __ldg(reinterpret_cast<const float4*>(m2 + (size_t)i1 * 128) + lane);
        const float4 r2 = __ldg(reinterpret_cast<const float4*>(m2 + (size_t)i2 * 128) + lane);
        const float4 r3 = __ldg(reinterpret_cast<const float4*>(m2 + (size_t)i3 * 128) + lane);

        // out_v1 = exp(<memory_v2[i], v1>/T); out_v2 = exp(<memory_v1[i], v2>/T)
        float u0 = DOT4(r0, a1), u1 = DOT4(r1, a1), u2 = DOT4(r2, a1), u3 = DOT4(r3, a1);
        float w0 = DOT4(q0, a2), w1 = DOT4(q1, a2), w2 = DOT4(q2, a2), w3 = DOT4(q3, a2);

        #pragma unroll
        for (int o = 16; o; o >>= 1) {
            u0 += __shfl_xor_sync(0xffffffffu, u0, o);
            u1 += __shfl_xor_sync(0xffffffffu, u1, o);
            u2 += __shfl_xor_sync(0xffffffffu, u2, o);
            u3 += __shfl_xor_sync(0xffffffffu, u3, o);
            w0 += __shfl_xor_sync(0xffffffffu, w0, o);
            w1 += __shfl_xor_sync(0xffffffffu, w1, o);
            w2 += __shfl_xor_sync(0xffffffffu, w2, o);
            w3 += __shfl_xor_sync(0xffffffffu, w3, o);
        }

        if (lane == 0) {
            const float eu[4] = { __expf(u0*invT), __expf(u1*invT), __expf(u2*invT), __expf(u3*invT) };
            const float ew[4] = { __expf(w0*invT), __expf(w1*invT), __expf(w2*invT), __expf(w3*invT) };
            #pragma unroll
            for (int j = 0; j < 4; ++j) {
                if (base + j < KP1) {
                    o1[base + j] = eu[j];
                    o2[base + j] = ew[j];
                    acc1 += (double)eu[j];
                    acc2 += (double)ew[j];
                }
            }
        }
    }

    if (lane == 0) { sred1[warp] = acc1; sred2[warp] = acc2; }
    __syncthreads();
    if (threadIdx.x == 0) {
        double t1 = 0.0, t2 = 0.0;
        #pragma unroll
        for (int j = 0; j < 8; ++j) { t1 += sred1[j]; t2 += sred2[j]; }
        atomicAdd(&g_sum[0], t1);
        atomicAdd(&g_sum[1], t2);
    }
}

// Copy both memory banks in one launch: first half of blocks -> bank 1,
// second half -> bank 2 (plain loads/stores; 83% DRAM measured).
__global__ void __launch_bounds__(256) copy_kernel(
    float4* __restrict__ d1, const float4* __restrict__ s1,
    float4* __restrict__ d2, const float4* __restrict__ s2,
    size_t n4, int halfGrid)
{
    const int half = (int)blockIdx.x < halfGrid ? 0 : 1;
    const float4* __restrict__ src = half ? s2 : s1;
    float4* __restrict__ dst = half ? d2 : d1;
    const int blk = half ? (int)blockIdx.x - halfGrid : (int)blockIdx.x;
    size_t i = (size_t)blk * blockDim.x + threadIdx.x;
    const size_t stride = (size_t)halfGrid * blockDim.x;
    for (; i < n4; i += stride) dst[i] = src[i];
}

// Fused epilogue: blocks [0, normBlocks) scale by precomputed g_scale (float),
// remaining blocks do the momentum scatter update (one warp per b).
__global__ void __launch_bounds__(256) epilogue_kernel(
    float* __restrict__ out1, float* __restrict__ out2, int total,
    const float* __restrict__ v1, const float* __restrict__ v2,
    const float* __restrict__ m1, const float* __restrict__ m2,
    const int* __restrict__ y,
    float* __restrict__ om1, float* __restrict__ om2,
    int B, int normBlocks)
{
    if ((int)blockIdx.x < normBlocks) {
        const float f1 = g_scale[0];
        const float f2 = g_scale[1];
        const int i = blockIdx.x * 256 + threadIdx.x;
        if (i < total) { out1[i] *= f1; out2[i] *= f2; }
        return;
    }

    const int warp = threadIdx.x >> 5;
    const int lane = threadIdx.x & 31;
    const int b = ((int)blockIdx.x - normBlocks) * 8 + warp;
    if (b >= B) return;
    const int yb = y[b];
    for (int b2 = b + 1; b2 < B; ++b2)
        if (y[b2] == yb) return;            // last duplicate wins

    {
        const float4 mv = reinterpret_cast<const float4*>(m1 + (size_t)yb * 128)[lane];
        const float4 vv = reinterpret_cast<const float4*>(v1 + (size_t)b  * 128)[lane];
        float4 p = { 0.5f*(mv.x+vv.x), 0.5f*(mv.y+vv.y), 0.5f*(mv.z+vv.z), 0.5f*(mv.w+vv.w) };
        float ss = p.x*p.x + p.y*p.y + p.z*p.z + p.w*p.w;
        #pragma unroll
        for (int o = 16; o; o >>= 1) ss += __shfl_xor_sync(0xffffffffu, ss, o);
        const float inv = 1.0f / sqrtf(ss);
        p.x *= inv; p.y *= inv; p.z *= inv; p.w *= inv;
        reinterpret_cast<float4*>(om1 + (size_t)yb * 128)[lane] = p;
    }
    {
        const float4 mv = reinterpret_cast<const float4*>(m2 + (size_t)yb * 128)[lane];
        const float4 vv = reinterpret_cast<const float4*>(v2 + (size_t)b  * 128)[lane];
        float4 p = { 0.5f*(mv.x+vv.x), 0.5f*(mv.y+vv.y), 0.5f*(mv.z+vv.z), 0.5f*(mv.w+vv.w) };
        float ss = p.x*p.x + p.y*p.y + p.z*p.z + p.w*p.w;
        #pragma unroll
        for (int o = 16; o; o >>= 1) ss += __shfl_xor_sync(0xffffffffu, ss, o);
        const float inv = 1.0f / sqrtf(ss);
        p.x *= inv; p.y *= inv; p.z *= inv; p.w *= inv;
        reinterpret_cast<float4*>(om2 + (size_t)yb * 128)[lane] = p;
    }
}

extern "C" void kernel_launch(void* const* d_in, const int* in_sizes, int n_in,
                              void* d_out, int out_size)
{
    const float* v1  = (const float*)d_in[0];
    const float* v2  = (const float*)d_in[1];
    const float* m1  = (const float*)d_in[2];
    const float* m2  = (const float*)d_in[3];
    const int*   y   = (const int*)d_in[4];
    const int*   idx = (const int*)d_in[5];

    const int B = in_sizes[4];                 // 256
    const int D = in_sizes[0] / B;             // 128
    const size_t ND = (size_t)in_sizes[2];     // N*D
    const int KP1 = in_sizes[5] / B;           // 4097
    const int Nout = (int)(ND / (size_t)D);    // 1,000,000

    float* out  = (float*)d_out;
    float* out1 = out;
    float* out2 = out + (size_t)B * KP1;
    float* om1  = out + 2 * (size_t)B * KP1;
    float* om2  = om1 + ND;

    init_sums_kernel<<<1, 1>>>();

    dot_exp_kernel<<<2 * B, 256>>>(v1, v2, m1, m2, y, idx, out1, out2, KP1);

    const int total = B * KP1;
    finalize_scale_kernel<<<1, 1>>>(total, (double)Nout);

    copy_kernel<<<2368, 256>>>((float4*)om1, (const float4*)m1,
                               (float4*)om2, (const float4*)m2, ND / 4, 1184);

    const int normBlocks = (total + 255) / 256;
    const int updBlocks = (B + 7) / 8;
    epilogue_kernel<<<normBlocks + updBlocks, 256>>>(
        out1, out2, total,
        v1, v2, m1, m2, y, om1, om2, B, normBlocks);
}

// round 4
// speedup vs baseline: 1.9728x; 1.4980x over previous
#include <cuda_runtime.h>
#include <cstddef>

// ---------------------------------------------------------------------------
// NCEAverageMultiview on GB300 — inverted-index formulation.
//
// Instead of 1.07 GB of random 512B gathers, build row -> (b,k) buckets, then
// ONE streaming pass over both memory banks does the copy AND all dot products
// (each bank row is read exactly once; v1/v2 stay hot in L2).
//
// d_out (fp32): out_v1 [B*KP1] | out_v2 [B*KP1] | new_mem_v1 [N*D] | new_mem_v2 [N*D]
// ---------------------------------------------------------------------------

#define MAXN 1100000
#define CAP  8
#define OVF_CAP 65536

__device__ int    g_count[MAXN];
__device__ int    g_entries[MAXN * CAP];
__device__ int    g_ovf[OVF_CAP];
__device__ int    g_ovf_n;
__device__ double g_sum[2];
__device__ float  g_scale[2];

#define DOT4(p, a) ((p).x*(a).x + (p).y*(a).y + (p).z*(a).z + (p).w*(a).w)

// Zero counts, overflow counter, sums.
__global__ void zero_kernel(int N) {
    const int i = blockIdx.x * blockDim.x + threadIdx.x;
    const int stride = gridDim.x * blockDim.x;
    for (int j = i; j < N; j += stride) g_count[j] = 0;
    if (i == 0) { g_ovf_n = 0; g_sum[0] = 0.0; g_sum[1] = 0.0; }
}

// Build row -> (b,k) buckets. Entry encode: (b << 13) | k  (k <= 4096 < 8192).
__global__ void histogram_kernel(const int* __restrict__ y,
                                 const int* __restrict__ idx, int KP1) {
    const int k = blockIdx.x * blockDim.x + threadIdx.x;
    const int b = blockIdx.y;
    if (k >= KP1) return;
    const int i = (k == 0) ? y[b] : idx[(size_t)b * KP1 + k];
    const int e = (b << 13) | k;
    const int slot = atomicAdd(&g_count[i], 1);
    if (slot < CAP) {
        g_entries[(size_t)i * CAP + slot] = e;
    } else {
        const int p = atomicAdd(&g_ovf_n, 1);
        if (p < OVF_CAP) g_ovf[p] = e;
    }
}

// Streaming pass: warp per row. Copy both bank rows; for each referencing
// (b,k), compute the two dots with the row data already in registers.
__global__ void __launch_bounds__(512) fused_kernel(
    const float* __restrict__ m1, const float* __restrict__ m2,
    const float* __restrict__ v1, const float* __restrict__ v2,
    float* __restrict__ om1, float* __restrict__ om2,
    float* __restrict__ out1, float* __restrict__ out2,
    int N, int KP1)
{
    __shared__ double sred1[16], sred2[16];
    const int lane = threadIdx.x & 31;
    const int warp = threadIdx.x >> 5;
    const int nWarps = gridDim.x * (blockDim.x >> 5);
    const int gw = blockIdx.x * (blockDim.x >> 5) + warp;
    const float invT = 1.0f / 0.07f;

    double acc1 = 0.0, acc2 = 0.0;

    for (int r = gw; r < N; r += nWarps) {
        const float4 x1 = __ldg(reinterpret_cast<const float4*>(m1 + (size_t)r * 128) + lane);
        const float4 x2 = __ldg(reinterpret_cast<const float4*>(m2 + (size_t)r * 128) + lane);
        reinterpret_cast<float4*>(om1 + (size_t)r * 128)[lane] = x1;
        reinterpret_cast<float4*>(om2 + (size_t)r * 128)[lane] = x2;

        int c = g_count[r];
        c = c < CAP ? c : CAP;
        for (int j = 0; j < c; ++j) {
            const int e = g_entries[(size_t)r * CAP + j];
            const int b = e >> 13;
            const int k = e & 8191;
            const float4 a1 = __ldg(reinterpret_cast<const float4*>(v1 + (size_t)b * 128) + lane);
            const float4 a2 = __ldg(reinterpret_cast<const float4*>(v2 + (size_t)b * 128) + lane);
            // out_v1 = exp(<m2[r], v1[b]>/T);  out_v2 = exp(<m1[r], v2[b]>/T)
            float s1 = DOT4(x2, a1);
            float s2 = DOT4(x1, a2);
            #pragma unroll
            for (int o = 16; o; o >>= 1) {
                s1 += __shfl_xor_sync(0xffffffffu, s1, o);
                s2 += __shfl_xor_sync(0xffffffffu, s2, o);
            }
            if (lane == 0) {
                const float e1 = __expf(s1 * invT);
                const float e2 = __expf(s2 * invT);
                out1[(size_t)b * KP1 + k] = e1;
                out2[(size_t)b * KP1 + k] = e2;
                acc1 += (double)e1;
                acc2 += (double)e2;
            }
        }
    }

    if (lane == 0) { sred1[warp] = acc1; sred2[warp] = acc2; }
    __syncthreads();
    if (threadIdx.x == 0) {
        double t1 = 0.0, t2 = 0.0;
        #pragma unroll
        for (int j = 0; j < 16; ++j) { t1 += sred1[j]; t2 += sred2[j]; }
        atomicAdd(&g_sum[0], t1);
        atomicAdd(&g_sum[1], t2);
    }
}

// Handle bucket-overflow entries the direct way (expected count: ~0-2).
__global__ void overflow_kernel(
    const float* __restrict__ m1, const float* __restrict__ m2,
    const float* __restrict__ v1, const float* __restrict__ v2,
    const int* __restrict__ y, const int* __restrict__ idx,
    float* __restrict__ out1, float* __restrict__ out2, int KP1)
{
    const int lane = threadIdx.x;  // 32 threads, 1 block
    const float invT = 1.0f / 0.07f;
    int n = g_ovf_n;
    n = n < OVF_CAP ? n : OVF_CAP;
    double acc1 = 0.0, acc2 = 0.0;
    for (int t = 0; t < n; ++t) {
        const int e = g_ovf[t];
        const int b = e >> 13;
        const int k = e & 8191;
        const int i = (k == 0) ? y[b] : idx[(size_t)b * KP1 + k];
        const float4 x1 = reinterpret_cast<const float4*>(m1 + (size_t)i * 128)[lane];
        const float4 x2 = reinterpret_cast<const float4*>(m2 + (size_t)i * 128)[lane];
        const float4 a1 = reinterpret_cast<const float4*>(v1 + (size_t)b * 128)[lane];
        const float4 a2 = reinterpret_cast<const float4*>(v2 + (size_t)b * 128)[lane];
        float s1 = DOT4(x2, a1);
        float s2 = DOT4(x1, a2);
        #pragma unroll
        for (int o = 16; o; o >>= 1) {
            s1 += __shfl_xor_sync(0xffffffffu, s1, o);
            s2 += __shfl_xor_sync(0xffffffffu, s2, o);
        }
        if (lane == 0) {
            const float e1 = __expf(s1 * invT);
            const float e2 = __expf(s2 * invT);
            out1[(size_t)b * KP1 + k] = e1;
            out2[(size_t)b * KP1 + k] = e2;
            acc1 += (double)e1;
            acc2 += (double)e2;
        }
    }
    if (lane == 0 && n > 0) {
        atomicAdd(&g_sum[0], acc1);
        atomicAdd(&g_sum[1], acc2);
    }
}

__global__ void finalize_scale_kernel(int total, double nOutput) {
    const double cnt = (double)total;
    g_scale[0] = (float)(cnt / (g_sum[0] * nOutput));
    g_scale[1] = (float)(cnt / (g_sum[1] * nOutput));
}

// Normalize outs (float scale) + momentum scatter update (one warp per b).
__global__ void __launch_bounds__(256) epilogue_kernel(
    float* __restrict__ out1, float* __restrict__ out2, int total,
    const float* __restrict__ v1, const float* __restrict__ v2,
    const float* __restrict__ m1, const float* __restrict__ m2,
    const int* __restrict__ y,
    float* __restrict__ om1, float* __restrict__ om2,
    int B, int normBlocks)
{
    if ((int)blockIdx.x < normBlocks) {
        const float f1 = g_scale[0];
        const float f2 = g_scale[1];
        const int i = blockIdx.x * 256 + threadIdx.x;
        if (i < total) { out1[i] *= f1; out2[i] *= f2; }
        return;
    }

    const int warp = threadIdx.x >> 5;
    const int lane = threadIdx.x & 31;
    const int b = ((int)blockIdx.x - normBlocks) * 8 + warp;
    if (b >= B) return;
    const int yb = y[b];
    for (int b2 = b + 1; b2 < B; ++b2)
        if (y[b2] == yb) return;            // last duplicate wins

    {
        const float4 mv = reinterpret_cast<const float4*>(m1 + (size_t)yb * 128)[lane];
        const float4 vv = reinterpret_cast<const float4*>(v1 + (size_t)b  * 128)[lane];
        float4 p = { 0.5f*(mv.x+vv.x), 0.5f*(mv.y+vv.y), 0.5f*(mv.z+vv.z), 0.5f*(mv.w+vv.w) };
        float ss = p.x*p.x + p.y*p.y + p.z*p.z + p.w*p.w;
        #pragma unroll
        for (int o = 16; o; o >>= 1) ss += __shfl_xor_sync(0xffffffffu, ss, o);
        const float inv = 1.0f / sqrtf(ss);
        p.x *= inv; p.y *= inv; p.z *= inv; p.w *= inv;
        reinterpret_cast<float4*>(om1 + (size_t)yb * 128)[lane] = p;
    }
    {
        const float4 mv = reinterpret_cast<const float4*>(m2 + (size_t)yb * 128)[lane];
        const float4 vv = reinterpret_cast<const float4*>(v2 + (size_t)b  * 128)[lane];
        float4 p = { 0.5f*(mv.x+vv.x), 0.5f*(mv.y+vv.y), 0.5f*(mv.z+vv.z), 0.5f*(mv.w+vv.w) };
        float ss = p.x*p.x + p.y*p.y + p.z*p.z + p.w*p.w;
        #pragma unroll
        for (int o = 16; o; o >>= 1) ss += __shfl_xor_sync(0xffffffffu, ss, o);
        const float inv = 1.0f / sqrtf(ss);
        p.x *= inv; p.y *= inv; p.z *= inv; p.w *= inv;
        reinterpret_cast<float4*>(om2 + (size_t)yb * 128)[lane] = p;
    }
}

extern "C" void kernel_launch(void* const* d_in, const int* in_sizes, int n_in,
                              void* d_out, int out_size)
{
    const float* v1  = (const float*)d_in[0];
    const float* v2  = (const float*)d_in[1];
    const float* m1  = (const float*)d_in[2];
    const float* m2  = (const float*)d_in[3];
    const int*   y   = (const int*)d_in[4];
    const int*   idx = (const int*)d_in[5];

    const int B = in_sizes[4];                 // 256
    const int D = in_sizes[0] / B;             // 128
    const size_t ND = (size_t)in_sizes[2];     // N*D
    const int KP1 = in_sizes[5] / B;           // 4097
    const int N = (int)(ND / (size_t)D);       // 1,000,000

    float* out  = (float*)d_out;
    float* out1 = out;
    float* out2 = out + (size_t)B * KP1;
    float* om1  = out + 2 * (size_t)B * KP1;
    float* om2  = om1 + ND;

    // 1) zero counts/sums
    zero_kernel<<<1024, 256>>>(N);

    // 2) inverted index build
    histogram_kernel<<<dim3((KP1 + 255) / 256, B), 256>>>(y, idx, KP1);

    // 3) streaming copy + all dot products
    fused_kernel<<<2048, 512>>>(m1, m2, v1, v2, om1, om2, out1, out2, N, KP1);

    // 4) overflow fix-up (expected empty)
    overflow_kernel<<<1, 32>>>(m1, m2, v1, v2, y, idx, out1, out2, KP1);

    // 5) scale factors
    const int total = B * KP1;
    finalize_scale_kernel<<<1, 1>>>(total, (double)N);

    // 6) normalize + momentum scatter update
    const int normBlocks = (total + 255) / 256;
    const int updBlocks = (B + 7) / 8;
    epilogue_kernel<<<normBlocks + updBlocks, 256>>>(
        out1, out2, total,
        v1, v2, m1, m2, y, om1, om2, B, normBlocks);
}